// round 5
// baseline (speedup 1.0000x reference)
#include <cuda_runtime.h>
#include <cuda_fp16.h>
#include <cstdint>

#define EMB_DIM 300
#define KP      304
#define NTOT    2048
#define MTOT    32768
#define MTILE   128
#define NCHUNK  128
#define NCHUNKS (NTOT / NCHUNK)       // 16
#define KSTEPS  19
#define ASTR    312                   // halves/row, conflict-free ldmatrix
#define BSTR    136
#define A_BYTES (MTILE * ASTR * 2)    // 79872
#define B_BYTES (KP * BSTR * 2)       // 82688
#define RED_BYTES 65536               // 128x128 fp32 partial-sum scratch
#define SMEM_BYTES (A_BYTES + B_BYTES + RED_BYTES)   // 228096 <= 232448
#define BTOT4   (KP * NCHUNK / 8)     // 4864 uint4 per B chunk
#define SCALE 45.254833995939045f

__device__ __half g_Wh[KP * NTOT];
__device__ float  g_bs[NTOT];

__global__ void prep(const float* __restrict__ W, const float* __restrict__ b) {
    int i = blockIdx.x * blockDim.x + threadIdx.x;
    if (i < KP * NTOT) {
        int k = i / NTOT, n = i % NTOT;
        g_Wh[i] = __float2half_rn((k < EMB_DIM) ? W[k * NTOT + n] : 0.0f);
    }
    if (i < NTOT) g_bs[i] = b[i] * SCALE;
}

__device__ __forceinline__ void ldm_x4(uint32_t* r, uint32_t a) {
    asm volatile("ldmatrix.sync.aligned.m8n8.x4.shared.b16 {%0,%1,%2,%3}, [%4];"
                 : "=r"(r[0]), "=r"(r[1]), "=r"(r[2]), "=r"(r[3]) : "r"(a));
}
__device__ __forceinline__ void ldm_x4_t(uint32_t* r, uint32_t a) {
    asm volatile("ldmatrix.sync.aligned.m8n8.x4.trans.shared.b16 {%0,%1,%2,%3}, [%4];"
                 : "=r"(r[0]), "=r"(r[1]), "=r"(r[2]), "=r"(r[3]) : "r"(a));
}
__device__ __forceinline__ void mma16816(float* d, const uint32_t* a, const uint32_t* b) {
    asm volatile("mma.sync.aligned.m16n8k16.row.col.f32.f16.f16.f32 "
                 "{%0,%1,%2,%3}, {%4,%5,%6,%7}, {%8,%9}, {%0,%1,%2,%3};"
                 : "+f"(d[0]), "+f"(d[1]), "+f"(d[2]), "+f"(d[3])
                 : "r"(a[0]), "r"(a[1]), "r"(a[2]), "r"(a[3]),
                   "r"(b[0]), "r"(b[1]));
}

// cp.async one B chunk (g_Wh[:, n0:n0+128]) into smem [k][n] rows of BSTR
__device__ __forceinline__ void cp_b(uint32_t bB, int n0, int t, int step) {
    for (int i = t; i < BTOT4; i += step) {
        int k = i >> 4, j = i & 15;
        uint32_t dst = bB + (uint32_t)k * (BSTR * 2) + (uint32_t)j * 16;
        size_t g = __cvta_generic_to_global(g_Wh + (size_t)k * NTOT + n0 + 8 * j);
        asm volatile("cp.async.cg.shared.global [%0], [%1], 16;" :: "r"(dst), "l"(g));
    }
}

__global__ __launch_bounds__(256, 1)
void gemm_kernel(const int* __restrict__ x, const float* __restrict__ emb,
                 float* __restrict__ out) {
    extern __shared__ __half sm[];
    __half* A_s   = sm;
    char*   redP  = (char*)sm + A_BYTES + B_BYTES;
    const uint32_t smem_u = (uint32_t)__cvta_generic_to_shared(sm);
    const uint32_t bBufU  = smem_u + A_BYTES;

    const int tid = threadIdx.x;
    const int m0  = blockIdx.x * MTILE;

    // B chunk 0 in flight immediately
    cp_b(bBufU, 0, tid, 256);
    asm volatile("cp.async.commit_group;" ::: "memory");

    // ---- gather A: 128 rows, 2 threads/row ----
    {
        int r = tid >> 1;
        int token = x[m0 + r];
        const float4* src = (const float4*)(emb + (size_t)token * EMB_DIM);
        __half* dstrow = A_s + r * ASTR;
        #pragma unroll
        for (int j = (tid & 1); j < 75; j += 2) {
            float4 v = src[j];
            __half2* d2 = (__half2*)(dstrow + 4 * j);
            d2[0] = __floats2half2_rn(v.x, v.y);
            d2[1] = __floats2half2_rn(v.z, v.w);
        }
        if (tid < MTILE) {
            __half2* zp = (__half2*)(A_s + tid * ASTR + 300);
            zp[0] = __half2half2(__float2half(0.0f));
            zp[1] = __half2half2(__float2half(0.0f));
        }
    }

    const int lane = tid & 31, wid = tid >> 5;
    const int kg = wid >> 2;            // 0: ks 0..9, 1: ks 10..18
    const int pw = wid & 3;             // partner-pair id
    const int wm = pw & 1;              // m64 group
    const int wn = pw >> 1;             // n64 group
    const int bq = lane >> 3, rq = lane & 7;
    const int ksBeg = kg ? 10 : 0, ksEnd = kg ? 19 : 10;

    uint32_t aBase = smem_u + (uint32_t)((wm * 64 + (bq & 1) * 8 + rq) * ASTR) * 2
                            + (uint32_t)(bq >> 1) * 16;
    uint32_t bBase = bBufU + (uint32_t)(((bq & 1) * 8 + rq) * BSTR) * 2
                           + (uint32_t)(wn * 128 + (bq >> 1) * 16);
    const uint32_t redLane = (uint32_t)pw * 16384u + (uint32_t)lane * 16u;

    asm volatile("cp.async.wait_group 0;" ::: "memory");
    __syncthreads();

    #pragma unroll 1
    for (int nc = 0; nc < NCHUNKS; ++nc) {
        float acc[4][8][4];
        #pragma unroll
        for (int mt = 0; mt < 4; ++mt)
            #pragma unroll
            for (int nt = 0; nt < 8; ++nt)
                #pragma unroll
                for (int q = 0; q < 4; ++q) acc[mt][nt][q] = 0.0f;

        // ---- mainloop: each warp its own k-range, m64 x n64 ----
        for (int ks = ksBeg; ks < ksEnd; ++ks) {
            uint32_t af[4][4], bf[4][4];
            uint32_t kbA = (uint32_t)ks * 32;
            uint32_t kbB = (uint32_t)ks * 16 * (BSTR * 2);
            #pragma unroll
            for (int mt = 0; mt < 4; ++mt)
                ldm_x4(af[mt], aBase + (uint32_t)(mt * 16 * ASTR) * 2 + kbA);
            #pragma unroll
            for (int p = 0; p < 4; ++p)
                ldm_x4_t(bf[p], bBase + (uint32_t)p * 32 + kbB);
            #pragma unroll
            for (int mt = 0; mt < 4; ++mt)
                #pragma unroll
                for (int nt = 0; nt < 8; ++nt) {
                    uint32_t bb[2] = { bf[nt >> 1][(nt & 1) * 2],
                                       bf[nt >> 1][(nt & 1) * 2 + 1] };
                    mma16816(acc[mt][nt], af[mt], bb);
                }
        }

        // ---- kg0 publishes partials to scratch ----
        if (kg == 0) {
            #pragma unroll
            for (int mt = 0; mt < 4; ++mt)
                #pragma unroll
                for (int nt = 0; nt < 8; ++nt) {
                    float4 v = { acc[mt][nt][0], acc[mt][nt][1],
                                 acc[mt][nt][2], acc[mt][nt][3] };
                    *(float4*)(redP + redLane + (uint32_t)(mt * 8 + nt) * 512u) = v;
                }
        }
        __syncthreads();   // scratch ready; B buffer free (all reads done)

        if (kg == 0) {
            // prefetch next B chunk while kg1 reduces/stores
            if (nc + 1 < NCHUNKS) cp_b(bBufU, (nc + 1) * NCHUNK, tid, 128);
            asm volatile("cp.async.commit_group;" ::: "memory");
            asm volatile("cp.async.wait_group 0;" ::: "memory");
        } else {
            // ---- kg1: combine, bias, scale, store ----
            int n0 = nc * NCHUNK;
            #pragma unroll
            for (int nt = 0; nt < 8; ++nt) {
                int col = n0 + wn * 64 + nt * 8 + (lane & 3) * 2;
                float2 cb = *(const float2*)(g_bs + col);
                #pragma unroll
                for (int mt = 0; mt < 4; ++mt) {
                    float4 pv = *(const float4*)(redP + redLane
                                 + (uint32_t)(mt * 8 + nt) * 512u);
                    int row = m0 + wm * 64 + mt * 16 + (lane >> 2);
                    float2 v0 = { fmaf(acc[mt][nt][0] + pv.x, SCALE, cb.x),
                                  fmaf(acc[mt][nt][1] + pv.y, SCALE, cb.y) };
                    float2 v1 = { fmaf(acc[mt][nt][2] + pv.z, SCALE, cb.x),
                                  fmaf(acc[mt][nt][3] + pv.w, SCALE, cb.y) };
                    *(float2*)(out + (size_t)row * NTOT + col)       = v0;
                    *(float2*)(out + (size_t)(row + 8) * NTOT + col) = v1;
                }
            }
        }
        __syncthreads();   // B chunk nc+1 resident; scratch reusable
    }
}

extern "C" void kernel_launch(void* const* d_in, const int* in_sizes, int n_in,
                              void* d_out, int out_size) {
    const int*   x    = (const int*)  d_in[0];
    const float* emb  = (const float*)d_in[1];
    const float* W    = (const float*)d_in[2];
    const float* bias = (const float*)d_in[3];
    float*       out  = (float*)      d_out;

    cudaFuncSetAttribute(gemm_kernel, cudaFuncAttributeMaxDynamicSharedMemorySize,
                         SMEM_BYTES);

    prep<<<(KP * NTOT + 255) / 256, 256>>>(W, bias);
    gemm_kernel<<<MTOT / MTILE, 256, SMEM_BYTES>>>(x, emb, out);
}

// round 7
// speedup vs baseline: 1.3011x; 1.3011x over previous
#include <cuda_runtime.h>
#include <cuda_fp16.h>
#include <cstdint>

#define EMB_DIM 300
#define KP      304                 // K padded to multiple of 16
#define NTOT    2048
#define MTOT    32768
#define MTILE   128
#define NCHUNK  128
#define NCHUNKS (NTOT / NCHUNK)     // 16
#define KSTEPS  19
#define ASTR    312                 // halves per A row (conflict-free ldmatrix)
#define BSTR    136                 // halves per B row (conflict-free ldmatrix)
#define A_BYTES (MTILE * ASTR * 2)  // 79872
#define B_BYTES (KP * BSTR * 2)     // 82688
#define SMEM_BYTES (A_BYTES + B_BYTES)  // 162560
#define NLD     19                  // uint4 B loads per thread per chunk (256 thr)
#define BTOT4   (KP * NCHUNK / 8)   // 4864 uint4 per chunk
#define SCALE 45.254833995939045f   // sqrt(2048)

__device__ __half g_Wh[KP * NTOT];  // fp16 W, K zero-padded
__device__ float  g_bs[NTOT];       // bias * scale

__global__ void prep(const float* __restrict__ W, const float* __restrict__ b) {
    int i = blockIdx.x * blockDim.x + threadIdx.x;
    if (i < KP * NTOT) {
        int k = i / NTOT, n = i % NTOT;
        g_Wh[i] = __float2half_rn((k < EMB_DIM) ? W[k * NTOT + n] : 0.0f);
    }
    if (i < NTOT) g_bs[i] = b[i] * SCALE;
}

__device__ __forceinline__ void ldm_x4(uint32_t* r, uint32_t a) {
    asm volatile("ldmatrix.sync.aligned.m8n8.x4.shared.b16 {%0,%1,%2,%3}, [%4];"
                 : "=r"(r[0]), "=r"(r[1]), "=r"(r[2]), "=r"(r[3]) : "r"(a));
}
__device__ __forceinline__ void ldm_x4_t(uint32_t* r, uint32_t a) {
    asm volatile("ldmatrix.sync.aligned.m8n8.x4.trans.shared.b16 {%0,%1,%2,%3}, [%4];"
                 : "=r"(r[0]), "=r"(r[1]), "=r"(r[2]), "=r"(r[3]) : "r"(a));
}
__device__ __forceinline__ void mma16816(float* d, const uint32_t* a, const uint32_t* b) {
    asm volatile("mma.sync.aligned.m16n8k16.row.col.f32.f16.f16.f32 "
                 "{%0,%1,%2,%3}, {%4,%5,%6,%7}, {%8,%9}, {%0,%1,%2,%3};"
                 : "+f"(d[0]), "+f"(d[1]), "+f"(d[2]), "+f"(d[3])
                 : "r"(a[0]), "r"(a[1]), "r"(a[2]), "r"(a[3]),
                   "r"(b[0]), "r"(b[1]));
}

__global__ __launch_bounds__(256, 1)
void gemm_kernel(const int* __restrict__ x, const float* __restrict__ emb,
                 float* __restrict__ out) {
    extern __shared__ __half sm[];
    __half* A_s = sm;                          // [MTILE][ASTR]
    __half* B_s = sm + MTILE * ASTR;           // [KP][BSTR]
    const uint32_t smem_u = (uint32_t)__cvta_generic_to_shared(sm);
    const uint32_t bBufU  = smem_u + A_BYTES;

    const int tid = threadIdx.x;
    const int m0  = blockIdx.x * MTILE;

    // ---- register prefetch of B chunk 0 (LDG in flight during A gather) ----
    uint4 breg[NLD];
    #pragma unroll
    for (int it = 0; it < NLD; ++it) {
        int i = tid + it * 256;
        if (i < BTOT4) {
            int k = i >> 4, j = i & 15;
            breg[it] = *(const uint4*)(g_Wh + (size_t)k * NTOT + 8 * j);
        }
    }

    // ---- Gather A: 128 rows, 2 threads/row, fp32 -> fp16 ----
    {
        int r = tid >> 1;
        int token = x[m0 + r];
        const float4* src = (const float4*)(emb + (size_t)token * EMB_DIM);
        __half* dstrow = A_s + r * ASTR;
        #pragma unroll
        for (int j = (tid & 1); j < 75; j += 2) {   // 75 float4 per row
            float4 v = src[j];
            __half2* d2 = (__half2*)(dstrow + 4 * j);
            d2[0] = __floats2half2_rn(v.x, v.y);
            d2[1] = __floats2half2_rn(v.z, v.w);
        }
        if (tid < MTILE) {                      // zero K pad 300..303
            __half2* zp = (__half2*)(A_s + tid * ASTR + 300);
            zp[0] = __half2half2(__float2half(0.0f));
            zp[1] = __half2half2(__float2half(0.0f));
        }
    }

    const int lane = tid & 31, wid = tid >> 5;   // 8 warps
    const int wm = wid & 1;         // 0..1 : m64 each
    const int wn = wid >> 1;        // 0..3 : n32 each
    const int bq = lane >> 3, rq = lane & 7;

    uint32_t aBase = smem_u + (uint32_t)((wm * 64 + (bq & 1) * 8 + rq) * ASTR) * 2
                            + (uint32_t)(bq >> 1) * 16;
    uint32_t bBase = bBufU + (uint32_t)(((bq & 1) * 8 + rq) * BSTR) * 2
                           + (uint32_t)(wn * 64 + (bq >> 1) * 16);

    #pragma unroll 1
    for (int nc = 0; nc < NCHUNKS; ++nc) {
        // ---- commit prefetched B regs to smem ----
        #pragma unroll
        for (int it = 0; it < NLD; ++it) {
            int i = tid + it * 256;
            if (i < BTOT4) {
                int k = i >> 4, j = i & 15;
                *(uint4*)((char*)B_s + (uint32_t)k * (BSTR * 2) + (uint32_t)j * 16) =
                    breg[it];
            }
        }
        __syncthreads();

        float acc[4][4][4];
        #pragma unroll
        for (int mt = 0; mt < 4; ++mt)
            #pragma unroll
            for (int nt = 0; nt < 4; ++nt)
                #pragma unroll
                for (int q = 0; q < 4; ++q) acc[mt][nt][q] = 0.0f;

        // ---- k-loop: m64 x n32 per warp, frag double-buffered ----
        uint32_t af[2][4][4], bf[2][2][4];
        #pragma unroll
        for (int mt = 0; mt < 4; ++mt)
            ldm_x4(af[0][mt], aBase + (uint32_t)(mt * 16 * ASTR) * 2);
        #pragma unroll
        for (int p = 0; p < 2; ++p)
            ldm_x4_t(bf[0][p], bBase + (uint32_t)p * 32);

        #pragma unroll
        for (int ks = 0; ks < KSTEPS; ++ks) {
            int cur = ks & 1, nxt = cur ^ 1;
            if (ks + 1 < KSTEPS) {
                uint32_t kbA = (uint32_t)(ks + 1) * 32;
                uint32_t kbB = (uint32_t)(ks + 1) * 16 * (BSTR * 2);
                #pragma unroll
                for (int mt = 0; mt < 4; ++mt)
                    ldm_x4(af[nxt][mt],
                           aBase + (uint32_t)(mt * 16 * ASTR) * 2 + kbA);
                #pragma unroll
                for (int p = 0; p < 2; ++p)
                    ldm_x4_t(bf[nxt][p], bBase + (uint32_t)p * 32 + kbB);
            }
            #pragma unroll
            for (int mt = 0; mt < 4; ++mt)
                #pragma unroll
                for (int nt = 0; nt < 4; ++nt) {
                    uint32_t bb[2] = { bf[cur][nt >> 1][(nt & 1) * 2],
                                       bf[cur][nt >> 1][(nt & 1) * 2 + 1] };
                    mma16816(acc[mt][nt], af[cur][mt], bb);
                }
        }

        // ---- prefetch next B chunk into regs (covered by epilogue) ----
        if (nc + 1 < NCHUNKS) {
            int n0n = (nc + 1) * NCHUNK;
            #pragma unroll
            for (int it = 0; it < NLD; ++it) {
                int i = tid + it * 256;
                if (i < BTOT4) {
                    int k = i >> 4, j = i & 15;
                    breg[it] = *(const uint4*)(g_Wh + (size_t)k * NTOT + n0n + 8 * j);
                }
            }
        }

        // ---- epilogue: out = fma(acc, scale, bias*scale) ----
        int n0 = nc * NCHUNK;
        #pragma unroll
        for (int nt = 0; nt < 4; ++nt) {
            int col = n0 + wn * 32 + nt * 8 + (lane & 3) * 2;
            float2 cb = *(const float2*)(g_bs + col);
            #pragma unroll
            for (int mt = 0; mt < 4; ++mt) {
                int row = m0 + wm * 64 + mt * 16 + (lane >> 2);
                float2 v0 = { fmaf(acc[mt][nt][0], SCALE, cb.x),
                              fmaf(acc[mt][nt][1], SCALE, cb.y) };
                float2 v1 = { fmaf(acc[mt][nt][2], SCALE, cb.x),
                              fmaf(acc[mt][nt][3], SCALE, cb.y) };
                *(float2*)(out + (size_t)row * NTOT + col)       = v0;
                *(float2*)(out + (size_t)(row + 8) * NTOT + col) = v1;
            }
        }
        __syncthreads();   // all reads of B_s done before next STS
    }
}

extern "C" void kernel_launch(void* const* d_in, const int* in_sizes, int n_in,
                              void* d_out, int out_size) {
    const int*   x    = (const int*)  d_in[0];
    const float* emb  = (const float*)d_in[1];
    const float* W    = (const float*)d_in[2];
    const float* bias = (const float*)d_in[3];
    float*       out  = (float*)      d_out;

    cudaFuncSetAttribute(gemm_kernel, cudaFuncAttributeMaxDynamicSharedMemorySize,
                         SMEM_BYTES);

    prep<<<(KP * NTOT + 255) / 256, 256>>>(W, bias);
    gemm_kernel<<<MTOT / MTILE, 256, SMEM_BYTES>>>(x, emb, out);
}